// round 16
// baseline (speedup 1.0000x reference)
#include <cuda_runtime.h>
#include <cuda_fp16.h>
#include <math.h>
#include <stdint.h>

typedef unsigned int u32;
typedef __half f16;

// Problem constants
#define Nn    2000
#define DIN   2
#define DOUT  64
#define EDIM  16
#define Bb    64
#define CIN   66                  // DIN+DOUT
#define CCOLS (Bb*CIN)            // 4224
#define KI    (3*CIN)             // 198
#define KPAD  208                 // 13*16
#define KC16  13
#define ORES  (2*DOUT)            // 128
#define WRJ   (KI*ORES)           // 25344
#define WUJ   (KI*DOUT)           // 12672
#define WRJP  (KPAD*ORES)         // 26624
#define WUJP  (KPAD*DOUT)         // 13312

// ---------------- scratch (device globals; zero-initialized) ---------------
__device__ __align__(256) f16   g_AS [(size_t)2*Nn*Nn];     // rows 0..1999 = A, 2000..3999 = A^2
__device__ __align__(256) f16   g_Xh [(size_t)Nn*CCOLS];
__device__ __align__(256) f16   g_Yh [(size_t)2*Nn*CCOLS];  // rows 0..1999 = Y1, 2000..3999 = Y2raw
__device__ __align__(256) f16   g_Wrh[(size_t)Nn*WRJP];     // rows 198..207 stay 0
__device__ __align__(256) f16   g_Wuh[(size_t)Nn*WUJP];
__device__ __align__(256) float g_Z  [(size_t)Nn*Bb*DOUT];

// ---------------- PTX macros ----------------------------------------------
#define LDSM4(R0,R1,R2,R3,addr) \
    asm volatile("ldmatrix.sync.aligned.m8n8.x4.shared.b16 {%0,%1,%2,%3},[%4];" \
        : "=r"(R0),"=r"(R1),"=r"(R2),"=r"(R3) : "r"(addr))
#define LDSM4T(R0,R1,R2,R3,addr) \
    asm volatile("ldmatrix.sync.aligned.m8n8.x4.trans.shared.b16 {%0,%1,%2,%3},[%4];" \
        : "=r"(R0),"=r"(R1),"=r"(R2),"=r"(R3) : "r"(addr))
#define MMA16816(C,A,B0,B1) \
    asm volatile("mma.sync.aligned.m16n8k16.row.col.f32.f16.f16.f32 " \
        "{%0,%1,%2,%3},{%4,%5,%6,%7},{%8,%9},{%0,%1,%2,%3};" \
        : "+f"(C[0]),"+f"(C[1]),"+f"(C[2]),"+f"(C[3]) \
        : "r"(A[0]),"r"(A[1]),"r"(A[2]),"r"(A[3]),"r"(B0),"r"(B1))
#define CP16(saddr,gptr) \
    asm volatile("cp.async.cg.shared.global [%0], [%1], 16;" :: "r"(saddr), "l"(gptr))

__device__ __forceinline__ float tanh_f(float v) {
    float r;
    asm("tanh.approx.f32 %0, %1;" : "=f"(r) : "f"(v));
    return r;
}
__device__ __forceinline__ float sigmoid_f(float v) {
    return fmaf(0.5f, tanh_f(0.5f*v), 0.5f);
}

// ---------------- adjacency: 8 rows per block ------------------------------
#define AROWS 8
#define ADJ_SMEM (AROWS*Nn*4 + AROWS*EDIM*4 + AROWS*4 + 64)
__global__ __launch_bounds__(256) void adj_softmax(const float* __restrict__ emb)
{
    extern __shared__ float ash[];
    float* row = ash;                       // [8][2000]
    float* em  = ash + AROWS*Nn;            // [8][16]
    float* inv = em + AROWS*EDIM;           // [8]

    int m0 = blockIdx.x * AROWS;
    int tid = threadIdx.x;
    int lane = tid & 31, warp = tid >> 5;

    if (tid < AROWS*EDIM) {
        int m = tid >> 4, e = tid & 15;
        em[m*EDIM + e] = emb[(m0 + m)*EDIM + e];
    }
    __syncthreads();

    for (int n = tid; n < Nn; n += 256) {
        float4 e0 = *(const float4*)&emb[n*EDIM + 0];
        float4 e1 = *(const float4*)&emb[n*EDIM + 4];
        float4 e2 = *(const float4*)&emb[n*EDIM + 8];
        float4 e3 = *(const float4*)&emb[n*EDIM + 12];
        #pragma unroll
        for (int m = 0; m < AROWS; m++) {
            const float* e = &em[m*EDIM];
            float d = e[0]*e0.x + e[1]*e0.y + e[2]*e0.z + e[3]*e0.w
                    + e[4]*e1.x + e[5]*e1.y + e[6]*e1.z + e[7]*e1.w
                    + e[8]*e2.x + e[9]*e2.y + e[10]*e2.z + e[11]*e2.w
                    + e[12]*e3.x + e[13]*e3.y + e[14]*e3.z + e[15]*e3.w;
            row[m*Nn + n] = fmaxf(d, 0.f);
        }
    }
    __syncthreads();

    if (warp < AROWS) {
        float* r = &row[warp*Nn];
        float mx = -1e30f;
        for (int n = lane; n < Nn; n += 32) mx = fmaxf(mx, r[n]);
        #pragma unroll
        for (int s = 16; s > 0; s >>= 1)
            mx = fmaxf(mx, __shfl_xor_sync(0xffffffffu, mx, s));
        float sum = 0.f;
        for (int n = lane; n < Nn; n += 32) {
            float e0 = __expf(r[n] - mx);
            r[n] = e0;
            sum += e0;
        }
        #pragma unroll
        for (int s = 16; s > 0; s >>= 1)
            sum += __shfl_xor_sync(0xffffffffu, sum, s);
        if (lane == 0) inv[warp] = 1.f / sum;
    }
    __syncthreads();

    for (int n = tid; n < Nn; n += 256) {
        #pragma unroll
        for (int m = 0; m < AROWS; m++)
            g_AS[(size_t)(m0 + m)*Nn + n] = __float2half(row[m*Nn + n] * inv[m]);
    }
}

// ---------------- pack xs = concat(x, state) -> fp16 -----------------------
__global__ __launch_bounds__(256) void pack_x0(const float* __restrict__ x,
                                               const float* __restrict__ st)
{
    int idx = blockIdx.x * 256 + threadIdx.x;
    if (idx >= Nn*CCOLS) return;
    int n = idx / CCOLS;
    int c = idx - n*CCOLS;
    int b = c / CIN, i = c - b*CIN;
    float v = (i < DIN) ? x[((size_t)b*Nn + n)*DIN + i]
                        : st[((size_t)b*Nn + n)*DOUT + (i - DIN)];
    g_Xh[idx] = __float2half(v);
}

// ---------------- tensor-core fp16 GEMM: Ch = f16(Ah@Bh) -------------------
// Tile 128x192x48, 256 threads (8 warps, 4M x 2N), warp tile 32x96.
// 3-stage cp.async pipeline (wait_group 1); occ 2; column-guarded.
#define BM    128
#define BN    192
#define BK    48
#define ASTR  56     // halves (48 + 8 pad)
#define BSTR  200    // halves (192 + 8 pad)
#define A_HI  0
#define B_HI  14336  // 128*56*2
#define STG_B 33536  // 14336 + 48*200*2
#define NSTG  3
#define GSMEM_B 100608   // max(3*STG_B, 128*196*4 epilogue)

__global__ __launch_bounds__(256, 2) void mma_gemm(
    const f16* __restrict__ Ah, const f16* __restrict__ Bh,
    f16* __restrict__ Ch, int M, int N, int K)
{
    extern __shared__ __align__(16) char smem_raw[];
    const u32 sbase = (u32)__cvta_generic_to_shared(smem_raw);

    int tid  = threadIdx.x;
    int lane = tid & 31;
    int warp = tid >> 5;
    int wm = warp & 3;
    int wn = warp >> 2;
    int lrow = lane & 7;
    int lsel = lane >> 3;

    int m0 = blockIdx.y * BM;
    int n0 = blockIdx.x * BN;

    float acc[2][12][4];
    #pragma unroll
    for (int i = 0; i < 2; i++)
        #pragma unroll
        for (int j = 0; j < 12; j++)
            #pragma unroll
            for (int r = 0; r < 4; r++) acc[i][j][r] = 0.f;

    const float4 z4 = make_float4(0.f,0.f,0.f,0.f);

    auto load_stage = [&](int stage, int k0) {
        u32 sb = sbase + stage*STG_B;
        // A: 128x48 halves = 768 vec16, 3/thread
        #pragma unroll
        for (int t = 0; t < 3; t++) {
            int idx = tid + t*256;
            int row = idx / 6;
            int col = (idx - row*6) << 3;
            u32 so = sb + A_HI + (row*ASTR + col)*2;
            int gr = m0 + row;
            if (gr < M && (k0 + col) < K)
                CP16(so, (const void*)(Ah + (size_t)gr*K + k0 + col));
            else
                *(float4*)(smem_raw + (so - sbase)) = z4;
        }
        // B: 48x192 halves = 1152 vec16, 4.5/thread (guarded)
        #pragma unroll
        for (int t = 0; t < 5; t++) {
            int idx = tid + t*256;
            if (idx >= 1152) break;
            int row = idx / 24;
            int col = (idx - row*24) << 3;
            u32 so = sb + B_HI + (row*BSTR + col)*2;
            int gk = k0 + row;
            int gc = n0 + col;
            if (gk < K && gc + 7 < N)
                CP16(so, (const void*)(Bh + (size_t)gk*N + gc));
            else
                *(float4*)(smem_raw + (so - sbase)) = z4;
        }
    };

    int KT = (K + BK - 1) / BK;
    load_stage(0, 0);
    asm volatile("cp.async.commit_group;");
    if (KT > 1) { load_stage(1, BK); }
    asm volatile("cp.async.commit_group;");

    for (int ks = 0; ks < KT; ks++) {
        if (ks == KT - 1) asm volatile("cp.async.wait_group 0;");
        else              asm volatile("cp.async.wait_group 1;");
        __syncthreads();
        if (ks + 2 < KT) {
            load_stage((ks + 2) % NSTG, (ks + 2)*BK);
            asm volatile("cp.async.commit_group;");
        } else {
            asm volatile("cp.async.commit_group;");   // keep group count in sync
        }
        u32 sb = sbase + (ks % NSTG)*STG_B;
        #pragma unroll
        for (int kk = 0; kk < BK; kk += 16) {
            u32 ah[2][4];
            #pragma unroll
            for (int mt = 0; mt < 2; mt++) {
                int row = wm*32 + mt*16 + lrow + (lsel & 1)*8;
                int col = kk + (lsel >> 1)*8;
                LDSM4(ah[mt][0], ah[mt][1], ah[mt][2], ah[mt][3],
                      sb + A_HI + (row*ASTR + col)*2);
            }
            #pragma unroll
            for (int p = 0; p < 6; p++) {
                int row = kk + lrow + (lsel & 1)*8;
                int col = wn*96 + p*16 + (lsel >> 1)*8;
                u32 t0,t1,t2,t3;
                LDSM4T(t0,t1,t2,t3, sb + B_HI + (row*BSTR + col)*2);
                MMA16816(acc[0][2*p],   ah[0], t0, t1);
                MMA16816(acc[1][2*p],   ah[1], t0, t1);
                MMA16816(acc[0][2*p+1], ah[0], t2, t3);
                MMA16816(acc[1][2*p+1], ah[1], t2, t3);
            }
        }
        __syncthreads();
    }

    float* sbuf = (float*)smem_raw;      // [128][196]
    int group = lane >> 2, tg = lane & 3;
    #pragma unroll
    for (int mt = 0; mt < 2; mt++) {
        #pragma unroll
        for (int half = 0; half < 2; half++) {
            int r = wm*32 + mt*16 + group + half*8;
            #pragma unroll
            for (int nt = 0; nt < 12; nt++) {
                int c = wn*96 + nt*8 + tg*2;
                sbuf[r*196 + c]     = acc[mt][nt][half*2+0];
                sbuf[r*196 + c + 1] = acc[mt][nt][half*2+1];
            }
        }
    }
    __syncthreads();

    #pragma unroll 4
    for (int t = 0; t < 24; t++) {
        int idx4 = tid + t*256;
        int r = idx4 / 48;
        int c4 = idx4 - r*48;
        int r_g = m0 + r;
        int c_g = n0 + c4*4;
        if (r_g >= M || c_g + 3 >= N) continue;
        size_t gi = (size_t)r_g*N + c_g;
        float4 v = *(float4*)&sbuf[r*196 + c4*4];
        f16 h[4];
        h[0] = __float2half(v.x); h[1] = __float2half(v.y);
        h[2] = __float2half(v.z); h[3] = __float2half(v.w);
        *(uint2*)&Ch[gi] = *(uint2*)h;
    }
}

// ---------------- per-node weight mix via MMA ------------------------------
#define EMBSTR 40
#define WSSTR  264
__global__ __launch_bounds__(256) void mix_mma(
    const float* __restrict__ emb, const float* __restrict__ W,
    f16* __restrict__ outh, int J, int JP)
{
    __shared__ __align__(16) f16 embS[64*EMBSTR];
    __shared__ __align__(16) f16 WS[16*WSSTR];
    __shared__ __align__(16) f16 outS[64*WSSTR];

    int tid = threadIdx.x, lane = tid & 31, warp = tid >> 5;
    int wm = warp & 3, wn = warp >> 2;
    int lrow = lane & 7, lsel = lane >> 3;
    int n0 = blockIdx.y * 64;
    int j0 = blockIdx.x * 256;

    for (int t = tid; t < 64*16; t += 256) {
        int r = t >> 4, e = t & 15;
        float v = (n0 + r < Nn) ? emb[(n0 + r)*EDIM + e] : 0.f;
        embS[r*EMBSTR + e] = __float2half(v);
    }
    for (int t = tid; t < 16*256; t += 256) {
        int e = t >> 8, c = t & 255;
        int j = j0 + c;
        float v = (j < J) ? W[(size_t)e*J + j] : 0.f;
        WS[e*WSSTR + c] = __float2half(v);
    }
    __syncthreads();

    const u32 sbE = (u32)__cvta_generic_to_shared(embS);
    const u32 sbW = (u32)__cvta_generic_to_shared(WS);

    float acc[16][4];
    #pragma unroll
    for (int j = 0; j < 16; j++)
        #pragma unroll
        for (int r = 0; r < 4; r++) acc[j][r] = 0.f;

    u32 ah[4];
    {
        int row = wm*16 + lrow + (lsel & 1)*8;
        int col = (lsel >> 1)*8;
        LDSM4(ah[0], ah[1], ah[2], ah[3], sbE + (row*EMBSTR + col)*2);
    }
    #pragma unroll
    for (int p = 0; p < 8; p++) {
        int brow = lrow + (lsel & 1)*8;
        int bcol = wn*128 + p*16 + (lsel >> 1)*8;
        u32 t0,t1,t2,t3;
        LDSM4T(t0,t1,t2,t3, sbW + (brow*WSSTR + bcol)*2);
        MMA16816(acc[2*p],   ah, t0, t1);
        MMA16816(acc[2*p+1], ah, t2, t3);
    }

    int group = lane >> 2, tg = lane & 3;
    #pragma unroll
    for (int p = 0; p < 8; p++)
        #pragma unroll
        for (int f = 0; f < 2; f++)
            #pragma unroll
            for (int half = 0; half < 2; half++) {
                int row = wm*16 + group + half*8;
                int col = wn*128 + p*16 + f*8 + tg*2;
                outS[row*WSSTR + col]     = __float2half(acc[2*p+f][half*2+0]);
                outS[row*WSSTR + col + 1] = __float2half(acc[2*p+f][half*2+1]);
            }
    __syncthreads();

    for (int q = tid; q < 64*64; q += 256) {
        int r = q >> 6, c4 = q & 63;
        int n = n0 + r;
        int j = j0 + c4*4;
        if (n >= Nn || j >= J) continue;
        *(uint2*)&outh[(size_t)n*JP + j] = *(uint2*)&outS[r*WSSTR + c4*4];
    }
}

// ---------------- gate: tensor-core per-node [64x208]@[208x128] ------------
#define XGST  216
#define GWSTR 136
#define G_XG  0
#define G_W   27648
#define G_BR  (27648 + 8704)
#define GATE_SMEM (G_BR + 512 + 64)

__global__ __launch_bounds__(128) void gate_kernel(
    const float* __restrict__ emb, const float* __restrict__ b_reset,
    const float* __restrict__ st)
{
    extern __shared__ __align__(16) char sm[];
    const u32 sb = (u32)__cvta_generic_to_shared(sm);
    f16* xg = (f16*)(sm + G_XG);
    float* br = (float*)(sm + G_BR);
    float* em = (float*)(sm + G_BR + 512);

    int n = blockIdx.x, tid = threadIdx.x;
    int lane = tid & 31, warp = tid >> 5;
    int wm = warp & 1, wn = warp >> 1;
    int lrow = lane & 7, lsel = lane >> 3;

    if (tid < EDIM) em[tid] = emb[n*EDIM + tid];
    __syncthreads();
    {
        float a = 0.f;
        #pragma unroll
        for (int e = 0; e < EDIM; e++) a += em[e] * b_reset[e*ORES + tid];
        br[tid] = a;
    }

    const f16* wr = g_Wrh + (size_t)n*WRJP;
    for (int v = tid; v < 256; v += 128) {
        int row = v >> 4, col = (v & 15) << 3;
        CP16(sb + G_W + (row*GWSTR + col)*2, wr + v*8);
    }
    asm volatile("cp.async.commit_group;");

    const f16* s0 = g_Xh + (size_t)n*CCOLS;
    const f16* s1 = g_Yh + (size_t)n*CCOLS;
    const f16* s2 = g_Yh + (size_t)(Nn + n)*CCOLS;
    for (int c = tid*2; c < CCOLS; c += 256) {
        int b = c / CIN, i = c - b*CIN;
        __half2 h0 = *(const __half2*)&s0[c];
        *(__half2*)&xg[b*XGST + 0*CIN + i] = h0;
        *(__half2*)&xg[b*XGST + 1*CIN + i] = *(const __half2*)&s1[c];
        __half2 h2 = *(const __half2*)&s2[c];
        float2 f0 = __half22float2(h0), f2 = __half22float2(h2);
        *(__half2*)&xg[b*XGST + 2*CIN + i] =
            __floats2half2_rn(2.f*f2.x - f0.x, 2.f*f2.y - f0.y);
    }
    for (int idx = tid; idx < 64*(KPAD - KI); idx += 128) {
        int b = idx / (KPAD - KI), r = idx - b*(KPAD - KI);
        xg[b*XGST + KI + r] = __float2half(0.f);
    }

    float acc[2][8][4];
    #pragma unroll
    for (int i = 0; i < 2; i++)
        #pragma unroll
        for (int j = 0; j < 8; j++)
            #pragma unroll
            for (int r = 0; r < 4; r++) acc[i][j][r] = 0.f;

    for (int kc = 0; kc < KC16; kc++) {
        asm volatile("cp.async.wait_group 0;");
        __syncthreads();
        if (kc + 1 < KC16) {
            const f16* src = wr + (kc + 1)*16*ORES;
            u32 dst = sb + G_W + ((kc + 1) & 1)*16*GWSTR*2;
            for (int v = tid; v < 256; v += 128) {
                int row = v >> 4, col = (v & 15) << 3;
                CP16(dst + (row*GWSTR + col)*2, src + v*8);
            }
        }
        asm volatile("cp.async.commit_group;");
        u32 wb = sb + G_W + (kc & 1)*16*GWSTR*2;
        u32 ah[2][4];
        #pragma unroll
        for (int mt = 0; mt < 2; mt++) {
            int row = wm*32 + mt*16 + lrow + (lsel & 1)*8;
            int col = kc*16 + (lsel >> 1)*8;
            LDSM4(ah[mt][0], ah[mt][1], ah[mt][2], ah[mt][3],
                  sb + G_XG + (row*XGST + col)*2);
        }
        #pragma unroll
        for (int p = 0; p < 4; p++) {
            int brow = lrow + (lsel & 1)*8;
            int bcol = wn*64 + p*16 + (lsel >> 1)*8;
            u32 t0,t1,t2,t3;
            LDSM4T(t0,t1,t2,t3, wb + (brow*GWSTR + bcol)*2);
            MMA16816(acc[0][2*p],   ah[0], t0, t1);
            MMA16816(acc[1][2*p],   ah[1], t0, t1);
            MMA16816(acc[0][2*p+1], ah[0], t2, t3);
            MMA16816(acc[1][2*p+1], ah[1], t2, t3);
        }
        __syncthreads();
    }

    int group = lane >> 2, tg = lane & 3;
    #pragma unroll
    for (int mt = 0; mt < 2; mt++)
        #pragma unroll
        for (int nt = 0; nt < 8; nt++)
            #pragma unroll
            for (int half = 0; half < 2; half++)
                #pragma unroll
                for (int j = 0; j < 2; j++) {
                    int b = wm*32 + mt*16 + group + half*8;
                    int o = wn*64 + nt*8 + tg*2 + j;
                    float zr = sigmoid_f(acc[mt][nt][half*2 + j] + br[o]);
                    if (o < DOUT) {
                        g_Z[((size_t)n*Bb + b)*DOUT + o] = zr;
                    } else {
                        int od = o - DOUT;
                        float rs = zr * st[((size_t)b*Nn + n)*DOUT + od];
                        g_Xh[(size_t)n*CCOLS + b*CIN + DIN + od] = __float2half(rs);
                    }
                }
}

// ---------------- final: tensor-core per-node [64x208]@[208x64] ------------
#define FWSTR 72
#define F_W   27648
#define F_BU  (27648 + 4608)
#define FIN_SMEM (F_BU + 256 + 64)

__global__ __launch_bounds__(128) void final_kernel(
    const float* __restrict__ emb, const float* __restrict__ b_update,
    const float* __restrict__ st, float* __restrict__ out)
{
    extern __shared__ __align__(16) char sm[];
    const u32 sb = (u32)__cvta_generic_to_shared(sm);
    f16* xg = (f16*)(sm + G_XG);
    float* bu = (float*)(sm + F_BU);
    float* em = (float*)(sm + F_BU + 256);

    int n = blockIdx.x, tid = threadIdx.x;
    int lane = tid & 31, warp = tid >> 5;
    int lrow = lane & 7, lsel = lane >> 3;

    if (tid < EDIM) em[tid] = emb[n*EDIM + tid];
    __syncthreads();
    if (tid < DOUT) {
        float a = 0.f;
        #pragma unroll
        for (int e = 0; e < EDIM; e++) a += em[e] * b_update[e*DOUT + tid];
        bu[tid] = a;
    }

    const f16* wu = g_Wuh + (size_t)n*WUJP;
    for (int v = tid; v < 128; v += 128) {
        int row = v >> 3, col = (v & 7) << 3;
        CP16(sb + F_W + (row*FWSTR + col)*2, wu + v*8);
    }
    asm volatile("cp.async.commit_group;");

    const f16* s0 = g_Xh + (size_t)n*CCOLS;
    const f16* s1 = g_Yh + (size_t)n*CCOLS;
    const f16* s2 = g_Yh + (size_t)(Nn + n)*CCOLS;
    for (int c = tid*2; c < CCOLS; c += 256) {
        int b = c / CIN, i = c - b*CIN;
        __half2 h0 = *(const __half2*)&s0[c];
        *(__half2*)&xg[b*XGST + 0*CIN + i] = h0;
        *(__half2*)&xg[b*XGST + 1*CIN + i] = *(const __half2*)&s1[c];
        __half2 h2 = *(const __half2*)&s2[c];
        float2 f0 = __half22float2(h0), f2 = __half22float2(h2);
        *(__half2*)&xg[b*XGST + 2*CIN + i] =
            __floats2half2_rn(2.f*f2.x - f0.x, 2.f*f2.y - f0.y);
    }
    for (int idx = tid; idx < 64*(KPAD - KI); idx += 128) {
        int b = idx / (KPAD - KI), r = idx - b*(KPAD - KI);
        xg[b*XGST + KI + r] = __float2half(0.f);
    }

    float acc[8][4];
    #pragma unroll
    for (int j = 0; j < 8; j++)
        #pragma unroll
        for (int r = 0; r < 4; r++) acc[j][r] = 0.f;

    for (int kc = 0; kc < KC16; kc++) {
        asm volatile("cp.async.wait_group 0;");
        __syncthreads();
        if (kc + 1 < KC16) {
            const f16* src = wu + (kc + 1)*16*DOUT;
            u32 dst = sb + F_W + ((kc + 1) & 1)*16*FWSTR*2;
            for (int v = tid; v < 128; v += 128) {
                int row = v >> 3, col = (v & 7) << 3;
                CP16(dst + (row*FWSTR + col)*2, src + v*8);
            }
        }
        asm volatile("cp.async.commit_group;");
        u32 wb = sb + F_W + (kc & 1)*16*FWSTR*2;
        u32 ah[4];
        {
            int row = warp*16 + lrow + (lsel & 1)*8;
            int col = kc*16 + (lsel >> 1)*8;
            LDSM4(ah[0], ah[1], ah[2], ah[3],
                  sb + G_XG + (row*XGST + col)*2);
        }
        #pragma unroll
        for (int p = 0; p < 4; p++) {
            int brow = lrow + (lsel & 1)*8;
            int bcol = p*16 + (lsel >> 1)*8;
            u32 t0,t1,t2,t3;
            LDSM4T(t0,t1,t2,t3, wb + (brow*FWSTR + bcol)*2);
            MMA16816(acc[2*p],   ah, t0, t1);
            MMA16816(acc[2*p+1], ah, t2, t3);
        }
        __syncthreads();
    }

    int group = lane >> 2, tg = lane & 3;
    #pragma unroll
    for (int nt = 0; nt < 8; nt++)
        #pragma unroll
        for (int half = 0; half < 2; half++)
            #pragma unroll
            for (int j = 0; j < 2; j++) {
                int b = warp*16 + group + half*8;
                int o = nt*8 + tg*2 + j;
                float hc = tanh_f(acc[nt][half*2 + j] + bu[o]);
                float z  = g_Z[((size_t)n*Bb + b)*DOUT + o];
                float s  = st[((size_t)b*Nn + n)*DOUT + o];
                out[((size_t)b*Nn + n)*DOUT + o] = z*s + (1.f - z)*hc;
            }
}

// ---------------- launch ---------------------------------------------------
extern "C" void kernel_launch(void* const* d_in, const int* in_sizes, int n_in,
                              void* d_out, int out_size)
{
    const float* x    = (const float*)d_in[0];
    const float* st   = (const float*)d_in[1];
    const float* emb  = (const float*)d_in[2];
    const float* Wr_w = (const float*)d_in[3];
    const float* Wu_w = (const float*)d_in[4];
    const float* br_b = (const float*)d_in[5];
    const float* bu_b = (const float*)d_in[6];
    float* out = (float*)d_out;

    f16 *pAS, *pXh, *pYh, *pWrh, *pWuh;
    cudaGetSymbolAddress((void**)&pAS,  g_AS);
    cudaGetSymbolAddress((void**)&pXh,  g_Xh);
    cudaGetSymbolAddress((void**)&pYh,  g_Yh);
    cudaGetSymbolAddress((void**)&pWrh, g_Wrh);
    cudaGetSymbolAddress((void**)&pWuh, g_Wuh);
    f16* pA2 = pAS + (size_t)Nn*Nn;     // A^2 block (rows 2000..3999)

    cudaFuncSetAttribute(adj_softmax,  cudaFuncAttributeMaxDynamicSharedMemorySize, ADJ_SMEM);
    cudaFuncSetAttribute(gate_kernel,  cudaFuncAttributeMaxDynamicSharedMemorySize, GATE_SMEM);
    cudaFuncSetAttribute(final_kernel, cudaFuncAttributeMaxDynamicSharedMemorySize, FIN_SMEM);
    cudaFuncSetAttribute(mma_gemm,     cudaFuncAttributeMaxDynamicSharedMemorySize, GSMEM_B);

    dim3 gA2((Nn + BN - 1)/BN, (Nn + BM - 1)/BM);        // (11, 16)
    dim3 gFused(CCOLS/BN, (2*Nn + BM - 1)/BM);           // (22, 32)
    dim3 gMixR((WRJ + 255)/256, (Nn + 63)/64);
    dim3 gMixU((WUJ + 255)/256, (Nn + 63)/64);

    // Launch order puts the fused conv GEMM at position 4 (the profiled slot).
    pack_x0<<<(Nn*CCOLS + 255)/256, 256>>>(x, st);                      // 1
    adj_softmax<<<Nn/AROWS, 256, ADJ_SMEM>>>(emb);                      // 2
    mma_gemm<<<gA2, 256, GSMEM_B>>>(pAS, pAS, pA2, Nn, Nn, Nn);         // 3: A2 = A@A
    mma_gemm<<<gFused, 256, GSMEM_B>>>(pAS, pXh, pYh, 2*Nn, CCOLS, Nn); // 4: [Y1;Y2raw]
    mix_mma<<<gMixR, 256>>>(emb, Wr_w, pWrh, WRJ, WRJP);                // 5
    mix_mma<<<gMixU, 256>>>(emb, Wu_w, pWuh, WUJ, WUJP);                // 6

    gate_kernel<<<Nn, 128, GATE_SMEM>>>(emb, br_b, st);                 // 7

    mma_gemm<<<gFused, 256, GSMEM_B>>>(pAS, pXh, pYh, 2*Nn, CCOLS, Nn); // 8

    final_kernel<<<Nn, 128, FIN_SMEM>>>(emb, bu_b, st, out);            // 9
}

// round 17
// speedup vs baseline: 1.3561x; 1.3561x over previous
#include <cuda_runtime.h>
#include <cuda_fp16.h>
#include <math.h>
#include <stdint.h>

typedef unsigned int u32;
typedef __half f16;

// Problem constants
#define Nn    2000
#define DIN   2
#define DOUT  64
#define EDIM  16
#define Bb    64
#define CIN   66                  // DIN+DOUT
#define CCOLS (Bb*CIN)            // 4224
#define KI    (3*CIN)             // 198
#define KPAD  208                 // 13*16
#define KC16  13
#define ORES  (2*DOUT)            // 128
#define WRJ   (KI*ORES)           // 25344
#define WUJ   (KI*DOUT)           // 12672
#define WRJP  (KPAD*ORES)         // 26624
#define WUJP  (KPAD*DOUT)         // 13312

// ---------------- scratch (device globals; zero-initialized) ---------------
__device__ __align__(256) f16   g_AS [(size_t)2*Nn*Nn];     // rows 0..1999 = A, 2000..3999 = A^2
__device__ __align__(256) f16   g_Xh [(size_t)Nn*CCOLS];
__device__ __align__(256) f16   g_Yh [(size_t)2*Nn*CCOLS];  // rows 0..1999 = Y1, 2000..3999 = Y2raw
__device__ __align__(256) f16   g_Wrh[(size_t)Nn*WRJP];     // rows 198..207 stay 0
__device__ __align__(256) f16   g_Wuh[(size_t)Nn*WUJP];
__device__ __align__(256) float g_Z  [(size_t)Nn*Bb*DOUT];

// ---------------- PTX macros ----------------------------------------------
#define LDSM4(R0,R1,R2,R3,addr) \
    asm volatile("ldmatrix.sync.aligned.m8n8.x4.shared.b16 {%0,%1,%2,%3},[%4];" \
        : "=r"(R0),"=r"(R1),"=r"(R2),"=r"(R3) : "r"(addr))
#define LDSM4T(R0,R1,R2,R3,addr) \
    asm volatile("ldmatrix.sync.aligned.m8n8.x4.trans.shared.b16 {%0,%1,%2,%3},[%4];" \
        : "=r"(R0),"=r"(R1),"=r"(R2),"=r"(R3) : "r"(addr))
#define MMA16816(C,A,B0,B1) \
    asm volatile("mma.sync.aligned.m16n8k16.row.col.f32.f16.f16.f32 " \
        "{%0,%1,%2,%3},{%4,%5,%6,%7},{%8,%9},{%0,%1,%2,%3};" \
        : "+f"(C[0]),"+f"(C[1]),"+f"(C[2]),"+f"(C[3]) \
        : "r"(A[0]),"r"(A[1]),"r"(A[2]),"r"(A[3]),"r"(B0),"r"(B1))
#define CP16(saddr,gptr) \
    asm volatile("cp.async.cg.shared.global [%0], [%1], 16;" :: "r"(saddr), "l"(gptr))

__device__ __forceinline__ float tanh_f(float v) {
    float r;
    asm("tanh.approx.f32 %0, %1;" : "=f"(r) : "f"(v));
    return r;
}
__device__ __forceinline__ float sigmoid_f(float v) {
    return fmaf(0.5f, tanh_f(0.5f*v), 0.5f);
}

// ---------------- merged: adjacency (blocks 0..249) + pack (rest) ----------
#define AROWS 8
#define ADJB  (Nn/AROWS)          // 250
#define PACKB 2048
#define ADJ_SMEM (AROWS*Nn*4 + AROWS*EDIM*4 + AROWS*4 + 64)
__global__ __launch_bounds__(256) void adj_pack(
    const float* __restrict__ emb, const float* __restrict__ x,
    const float* __restrict__ st)
{
    int tid = threadIdx.x;
    if (blockIdx.x >= ADJB) {
        // ---- pack xs = concat(x, state) -> fp16, grid-stride ----
        int bid = blockIdx.x - ADJB;
        for (int idx = bid*256 + tid; idx < Nn*CCOLS; idx += PACKB*256) {
            int n = idx / CCOLS;
            int c = idx - n*CCOLS;
            int b = c / CIN, i = c - b*CIN;
            float v = (i < DIN) ? x[((size_t)b*Nn + n)*DIN + i]
                                : st[((size_t)b*Nn + n)*DOUT + (i - DIN)];
            g_Xh[idx] = __float2half(v);
        }
        return;
    }
    // ---- adjacency rows ----
    extern __shared__ float ash[];
    float* row = ash;                       // [8][2000]
    float* em  = ash + AROWS*Nn;            // [8][16]
    float* inv = em + AROWS*EDIM;           // [8]

    int m0 = blockIdx.x * AROWS;
    int lane = tid & 31, warp = tid >> 5;

    if (tid < AROWS*EDIM) {
        int m = tid >> 4, e = tid & 15;
        em[m*EDIM + e] = emb[(m0 + m)*EDIM + e];
    }
    __syncthreads();

    for (int n = tid; n < Nn; n += 256) {
        float4 e0 = *(const float4*)&emb[n*EDIM + 0];
        float4 e1 = *(const float4*)&emb[n*EDIM + 4];
        float4 e2 = *(const float4*)&emb[n*EDIM + 8];
        float4 e3 = *(const float4*)&emb[n*EDIM + 12];
        #pragma unroll
        for (int m = 0; m < AROWS; m++) {
            const float* e = &em[m*EDIM];
            float d = e[0]*e0.x + e[1]*e0.y + e[2]*e0.z + e[3]*e0.w
                    + e[4]*e1.x + e[5]*e1.y + e[6]*e1.z + e[7]*e1.w
                    + e[8]*e2.x + e[9]*e2.y + e[10]*e2.z + e[11]*e2.w
                    + e[12]*e3.x + e[13]*e3.y + e[14]*e3.z + e[15]*e3.w;
            row[m*Nn + n] = fmaxf(d, 0.f);
        }
    }
    __syncthreads();

    if (warp < AROWS) {
        float* r = &row[warp*Nn];
        float mx = -1e30f;
        for (int n = lane; n < Nn; n += 32) mx = fmaxf(mx, r[n]);
        #pragma unroll
        for (int s = 16; s > 0; s >>= 1)
            mx = fmaxf(mx, __shfl_xor_sync(0xffffffffu, mx, s));
        float sum = 0.f;
        for (int n = lane; n < Nn; n += 32) {
            float e0 = __expf(r[n] - mx);
            r[n] = e0;
            sum += e0;
        }
        #pragma unroll
        for (int s = 16; s > 0; s >>= 1)
            sum += __shfl_xor_sync(0xffffffffu, sum, s);
        if (lane == 0) inv[warp] = 1.f / sum;
    }
    __syncthreads();

    for (int n = tid; n < Nn; n += 256) {
        #pragma unroll
        for (int m = 0; m < AROWS; m++)
            g_AS[(size_t)(m0 + m)*Nn + n] = __float2half(row[m*Nn + n] * inv[m]);
    }
}

// ---------------- tensor-core fp16 GEMM: Ch = f16(Ah@Bh) -------------------
// Tile 128x192x64, 256 threads (8 warps, 4M x 2N), warp tile 32x96.
// 2-stage cp.async; occ 2; column-guarded. (R15-proven config.)
#define BM    128
#define BN    192
#define BK    64
#define ASTR  72
#define BSTR  200
#define A_HI  0
#define B_HI  18432
#define STG_B 44032
#define GSMEM_B 100352

__global__ __launch_bounds__(256, 2) void mma_gemm(
    const f16* __restrict__ Ah, const f16* __restrict__ Bh,
    f16* __restrict__ Ch, int M, int N, int K)
{
    extern __shared__ __align__(16) char smem_raw[];
    const u32 sbase = (u32)__cvta_generic_to_shared(smem_raw);

    int tid  = threadIdx.x;
    int lane = tid & 31;
    int warp = tid >> 5;
    int wm = warp & 3;
    int wn = warp >> 2;
    int lrow = lane & 7;
    int lsel = lane >> 3;

    int m0 = blockIdx.y * BM;
    int n0 = blockIdx.x * BN;

    float acc[2][12][4];
    #pragma unroll
    for (int i = 0; i < 2; i++)
        #pragma unroll
        for (int j = 0; j < 12; j++)
            #pragma unroll
            for (int r = 0; r < 4; r++) acc[i][j][r] = 0.f;

    const float4 z4 = make_float4(0.f,0.f,0.f,0.f);

    auto load_stage = [&](int stage, int k0) {
        u32 sb = sbase + stage*STG_B;
        #pragma unroll
        for (int t = 0; t < 4; t++) {
            int idx = tid + t*256;
            int row = idx >> 3;
            int col = (idx & 7) << 3;
            u32 so = sb + A_HI + (row*ASTR + col)*2;
            int gr = m0 + row;
            if (gr < M && (k0 + col) < K)
                CP16(so, (const void*)(Ah + (size_t)gr*K + k0 + col));
            else
                *(float4*)(smem_raw + (so - sbase)) = z4;
        }
        #pragma unroll
        for (int t = 0; t < 6; t++) {
            int idx = tid + t*256;
            int row = idx / 24;
            int col = (idx - row*24) << 3;
            u32 so = sb + B_HI + (row*BSTR + col)*2;
            int gk = k0 + row;
            int gc = n0 + col;
            if (gk < K && gc + 7 < N)
                CP16(so, (const void*)(Bh + (size_t)gk*N + gc));
            else
                *(float4*)(smem_raw + (so - sbase)) = z4;
        }
    };

    int KT = (K + BK - 1) / BK;
    load_stage(0, 0);
    asm volatile("cp.async.commit_group;");

    for (int ks = 0; ks < KT; ks++) {
        asm volatile("cp.async.wait_group 0;");
        __syncthreads();
        if (ks + 1 < KT) {
            load_stage((ks + 1) & 1, (ks + 1)*BK);
            asm volatile("cp.async.commit_group;");
        }
        u32 sb = sbase + (ks & 1)*STG_B;
        #pragma unroll
        for (int kk = 0; kk < BK; kk += 16) {
            u32 ah[2][4];
            #pragma unroll
            for (int mt = 0; mt < 2; mt++) {
                int row = wm*32 + mt*16 + lrow + (lsel & 1)*8;
                int col = kk + (lsel >> 1)*8;
                LDSM4(ah[mt][0], ah[mt][1], ah[mt][2], ah[mt][3],
                      sb + A_HI + (row*ASTR + col)*2);
            }
            #pragma unroll
            for (int p = 0; p < 6; p++) {
                int row = kk + lrow + (lsel & 1)*8;
                int col = wn*96 + p*16 + (lsel >> 1)*8;
                u32 t0,t1,t2,t3;
                LDSM4T(t0,t1,t2,t3, sb + B_HI + (row*BSTR + col)*2);
                MMA16816(acc[0][2*p],   ah[0], t0, t1);
                MMA16816(acc[1][2*p],   ah[1], t0, t1);
                MMA16816(acc[0][2*p+1], ah[0], t2, t3);
                MMA16816(acc[1][2*p+1], ah[1], t2, t3);
            }
        }
    }
    __syncthreads();

    float* sbuf = (float*)smem_raw;      // [128][196]
    int group = lane >> 2, tg = lane & 3;
    #pragma unroll
    for (int mt = 0; mt < 2; mt++) {
        #pragma unroll
        for (int half = 0; half < 2; half++) {
            int r = wm*32 + mt*16 + group + half*8;
            #pragma unroll
            for (int nt = 0; nt < 12; nt++) {
                int c = wn*96 + nt*8 + tg*2;
                sbuf[r*196 + c]     = acc[mt][nt][half*2+0];
                sbuf[r*196 + c + 1] = acc[mt][nt][half*2+1];
            }
        }
    }
    __syncthreads();

    #pragma unroll 4
    for (int t = 0; t < 24; t++) {
        int idx4 = tid + t*256;
        int r = idx4 / 48;
        int c4 = idx4 - r*48;
        int r_g = m0 + r;
        int c_g = n0 + c4*4;
        if (r_g >= M || c_g + 3 >= N) continue;
        size_t gi = (size_t)r_g*N + c_g;
        float4 v = *(float4*)&sbuf[r*196 + c4*4];
        f16 h[4];
        h[0] = __float2half(v.x); h[1] = __float2half(v.y);
        h[2] = __float2half(v.z); h[3] = __float2half(v.w);
        *(uint2*)&Ch[gi] = *(uint2*)h;
    }
}

// ---------------- per-node weight mix via MMA (z=0: Wr, z=1: Wu) -----------
#define EMBSTR 40
#define WSSTR  264
__global__ __launch_bounds__(256) void mix_mma(
    const float* __restrict__ emb,
    const float* __restrict__ Wr, const float* __restrict__ Wu)
{
    const float* W;
    f16* outh;
    int J, JP;
    if (blockIdx.z == 0) {
        W = Wr; outh = g_Wrh; J = WRJ; JP = WRJP;
    } else {
        if (blockIdx.x >= 50) return;      // Wu needs 50 x-blocks
        W = Wu; outh = g_Wuh; J = WUJ; JP = WUJP;
    }

    __shared__ __align__(16) f16 embS[64*EMBSTR];
    __shared__ __align__(16) f16 WS[16*WSSTR];
    __shared__ __align__(16) f16 outS[64*WSSTR];

    int tid = threadIdx.x, lane = tid & 31, warp = tid >> 5;
    int wm = warp & 3, wn = warp >> 2;
    int lrow = lane & 7, lsel = lane >> 3;
    int n0 = blockIdx.y * 64;
    int j0 = blockIdx.x * 256;

    for (int t = tid; t < 64*16; t += 256) {
        int r = t >> 4, e = t & 15;
        float v = (n0 + r < Nn) ? emb[(n0 + r)*EDIM + e] : 0.f;
        embS[r*EMBSTR + e] = __float2half(v);
    }
    for (int t = tid; t < 16*256; t += 256) {
        int e = t >> 8, c = t & 255;
        int j = j0 + c;
        float v = (j < J) ? W[(size_t)e*J + j] : 0.f;
        WS[e*WSSTR + c] = __float2half(v);
    }
    __syncthreads();

    const u32 sbE = (u32)__cvta_generic_to_shared(embS);
    const u32 sbW = (u32)__cvta_generic_to_shared(WS);

    float acc[16][4];
    #pragma unroll
    for (int j = 0; j < 16; j++)
        #pragma unroll
        for (int r = 0; r < 4; r++) acc[j][r] = 0.f;

    u32 ah[4];
    {
        int row = wm*16 + lrow + (lsel & 1)*8;
        int col = (lsel >> 1)*8;
        LDSM4(ah[0], ah[1], ah[2], ah[3], sbE + (row*EMBSTR + col)*2);
    }
    #pragma unroll
    for (int p = 0; p < 8; p++) {
        int brow = lrow + (lsel & 1)*8;
        int bcol = wn*128 + p*16 + (lsel >> 1)*8;
        u32 t0,t1,t2,t3;
        LDSM4T(t0,t1,t2,t3, sbW + (brow*WSSTR + bcol)*2);
        MMA16816(acc[2*p],   ah, t0, t1);
        MMA16816(acc[2*p+1], ah, t2, t3);
    }

    int group = lane >> 2, tg = lane & 3;
    #pragma unroll
    for (int p = 0; p < 8; p++)
        #pragma unroll
        for (int f = 0; f < 2; f++)
            #pragma unroll
            for (int half = 0; half < 2; half++) {
                int row = wm*16 + group + half*8;
                int col = wn*128 + p*16 + f*8 + tg*2;
                outS[row*WSSTR + col]     = __float2half(acc[2*p+f][half*2+0]);
                outS[row*WSSTR + col + 1] = __float2half(acc[2*p+f][half*2+1]);
            }
    __syncthreads();

    for (int q = tid; q < 64*64; q += 256) {
        int r = q >> 6, c4 = q & 63;
        int n = n0 + r;
        int j = j0 + c4*4;
        if (n >= Nn || j >= J) continue;
        *(uint2*)&outh[(size_t)n*JP + j] = *(uint2*)&outS[r*WSSTR + c4*4];
    }
}

// ---------------- gate: tensor-core per-node [64x208]@[208x128] ------------
#define XGST  216
#define GWSTR 136
#define G_XG  0
#define G_W   27648
#define G_BR  (27648 + 8704)
#define GATE_SMEM (G_BR + 512 + 64)

__global__ __launch_bounds__(128) void gate_kernel(
    const float* __restrict__ emb, const float* __restrict__ b_reset,
    const float* __restrict__ st)
{
    extern __shared__ __align__(16) char sm[];
    const u32 sb = (u32)__cvta_generic_to_shared(sm);
    f16* xg = (f16*)(sm + G_XG);
    float* br = (float*)(sm + G_BR);
    float* em = (float*)(sm + G_BR + 512);

    int n = blockIdx.x, tid = threadIdx.x;
    int lane = tid & 31, warp = tid >> 5;
    int wm = warp & 1, wn = warp >> 1;
    int lrow = lane & 7, lsel = lane >> 3;

    if (tid < EDIM) em[tid] = emb[n*EDIM + tid];
    __syncthreads();
    {
        float a = 0.f;
        #pragma unroll
        for (int e = 0; e < EDIM; e++) a += em[e] * b_reset[e*ORES + tid];
        br[tid] = a;
    }

    const f16* wr = g_Wrh + (size_t)n*WRJP;
    for (int v = tid; v < 256; v += 128) {
        int row = v >> 4, col = (v & 15) << 3;
        CP16(sb + G_W + (row*GWSTR + col)*2, wr + v*8);
    }
    asm volatile("cp.async.commit_group;");

    const f16* s0 = g_Xh + (size_t)n*CCOLS;
    const f16* s1 = g_Yh + (size_t)n*CCOLS;
    const f16* s2 = g_Yh + (size_t)(Nn + n)*CCOLS;
    for (int c = tid*2; c < CCOLS; c += 256) {
        int b = c / CIN, i = c - b*CIN;
        __half2 h0 = *(const __half2*)&s0[c];
        *(__half2*)&xg[b*XGST + 0*CIN + i] = h0;
        *(__half2*)&xg[b*XGST + 1*CIN + i] = *(const __half2*)&s1[c];
        __half2 h2 = *(const __half2*)&s2[c];
        float2 f0 = __half22float2(h0), f2 = __half22float2(h2);
        *(__half2*)&xg[b*XGST + 2*CIN + i] =
            __floats2half2_rn(2.f*f2.x - f0.x, 2.f*f2.y - f0.y);
    }
    for (int idx = tid; idx < 64*(KPAD - KI); idx += 128) {
        int b = idx / (KPAD - KI), r = idx - b*(KPAD - KI);
        xg[b*XGST + KI + r] = __float2half(0.f);
    }

    float acc[2][8][4];
    #pragma unroll
    for (int i = 0; i < 2; i++)
        #pragma unroll
        for (int j = 0; j < 8; j++)
            #pragma unroll
            for (int r = 0; r < 4; r++) acc[i][j][r] = 0.f;

    for (int kc = 0; kc < KC16; kc++) {
        asm volatile("cp.async.wait_group 0;");
        __syncthreads();
        if (kc + 1 < KC16) {
            const f16* src = wr + (kc + 1)*16*ORES;
            u32 dst = sb + G_W + ((kc + 1) & 1)*16*GWSTR*2;
            for (int v = tid; v < 256; v += 128) {
                int row = v >> 4, col = (v & 15) << 3;
                CP16(dst + (row*GWSTR + col)*2, src + v*8);
            }
        }
        asm volatile("cp.async.commit_group;");
        u32 wb = sb + G_W + (kc & 1)*16*GWSTR*2;
        u32 ah[2][4];
        #pragma unroll
        for (int mt = 0; mt < 2; mt++) {
            int row = wm*32 + mt*16 + lrow + (lsel & 1)*8;
            int col = kc*16 + (lsel >> 1)*8;
            LDSM4(ah[mt][0], ah[mt][1], ah[mt][2], ah[mt][3],
                  sb + G_XG + (row*XGST + col)*2);
        }
        #pragma unroll
        for (int p = 0; p < 4; p++) {
            int brow = lrow + (lsel & 1)*8;
            int bcol = wn*64 + p*16 + (lsel >> 1)*8;
            u32 t0,t1,t2,t3;
            LDSM4T(t0,t1,t2,t3, wb + (brow*GWSTR + bcol)*2);
            MMA16816(acc[0][2*p],   ah[0], t0, t1);
            MMA16816(acc[1][2*p],   ah[1], t0, t1);
            MMA16816(acc[0][2*p+1], ah[0], t2, t3);
            MMA16816(acc[1][2*p+1], ah[1], t2, t3);
        }
        __syncthreads();
    }

    int group = lane >> 2, tg = lane & 3;
    #pragma unroll
    for (int mt = 0; mt < 2; mt++)
        #pragma unroll
        for (int nt = 0; nt < 8; nt++)
            #pragma unroll
            for (int half = 0; half < 2; half++)
                #pragma unroll
                for (int j = 0; j < 2; j++) {
                    int b = wm*32 + mt*16 + group + half*8;
                    int o = wn*64 + nt*8 + tg*2 + j;
                    float zr = sigmoid_f(acc[mt][nt][half*2 + j] + br[o]);
                    if (o < DOUT) {
                        g_Z[((size_t)n*Bb + b)*DOUT + o] = zr;
                    } else {
                        int od = o - DOUT;
                        float rs = zr * st[((size_t)b*Nn + n)*DOUT + od];
                        g_Xh[(size_t)n*CCOLS + b*CIN + DIN + od] = __float2half(rs);
                    }
                }
}

// ---------------- final: tensor-core per-node [64x208]@[208x64] ------------
#define FWSTR 72
#define F_W   27648
#define F_BU  (27648 + 4608)
#define FIN_SMEM (F_BU + 256 + 64)

__global__ __launch_bounds__(128) void final_kernel(
    const float* __restrict__ emb, const float* __restrict__ b_update,
    const float* __restrict__ st, float* __restrict__ out)
{
    extern __shared__ __align__(16) char sm[];
    const u32 sb = (u32)__cvta_generic_to_shared(sm);
    f16* xg = (f16*)(sm + G_XG);
    float* bu = (float*)(sm + F_BU);
    float* em = (float*)(sm + F_BU + 256);

    int n = blockIdx.x, tid = threadIdx.x;
    int lane = tid & 31, warp = tid >> 5;
    int lrow = lane & 7, lsel = lane >> 3;

    if (tid < EDIM) em[tid] = emb[n*EDIM + tid];
    __syncthreads();
    if (tid < DOUT) {
        float a = 0.f;
        #pragma unroll
        for (int e = 0; e < EDIM; e++) a += em[e] * b_update[e*DOUT + tid];
        bu[tid] = a;
    }

    const f16* wu = g_Wuh + (size_t)n*WUJP;
    for (int v = tid; v < 128; v += 128) {
        int row = v >> 3, col = (v & 7) << 3;
        CP16(sb + F_W + (row*FWSTR + col)*2, wu + v*8);
    }
    asm volatile("cp.async.commit_group;");

    const f16* s0 = g_Xh + (size_t)n*CCOLS;
    const f16* s1 = g_Yh + (size_t)n*CCOLS;
    const f16* s2 = g_Yh + (size_t)(Nn + n)*CCOLS;
    for (int c = tid*2; c < CCOLS; c += 256) {
        int b = c / CIN, i = c - b*CIN;
        __half2 h0 = *(const __half2*)&s0[c];
        *(__half2*)&xg[b*XGST + 0*CIN + i] = h0;
        *(__half2*)&xg[b*XGST + 1*CIN + i] = *(const __half2*)&s1[c];
        __half2 h2 = *(const __half2*)&s2[c];
        float2 f0 = __half22float2(h0), f2 = __half22float2(h2);
        *(__half2*)&xg[b*XGST + 2*CIN + i] =
            __floats2half2_rn(2.f*f2.x - f0.x, 2.f*f2.y - f0.y);
    }
    for (int idx = tid; idx < 64*(KPAD - KI); idx += 128) {
        int b = idx / (KPAD - KI), r = idx - b*(KPAD - KI);
        xg[b*XGST + KI + r] = __float2half(0.f);
    }

    float acc[8][4];
    #pragma unroll
    for (int j = 0; j < 8; j++)
        #pragma unroll
        for (int r = 0; r < 4; r++) acc[j][r] = 0.f;

    for (int kc = 0; kc < KC16; kc++) {
        asm volatile("cp.async.wait_group 0;");
        __syncthreads();
        if (kc + 1 < KC16) {
            const f16* src = wu + (kc + 1)*16*DOUT;
            u32 dst = sb + F_W + ((kc + 1) & 1)*16*FWSTR*2;
            for (int v = tid; v < 128; v += 128) {
                int row = v >> 3, col = (v & 7) << 3;
                CP16(dst + (row*FWSTR + col)*2, src + v*8);
            }
        }
        asm volatile("cp.async.commit_group;");
        u32 wb = sb + F_W + (kc & 1)*16*FWSTR*2;
        u32 ah[4];
        {
            int row = warp*16 + lrow + (lsel & 1)*8;
            int col = kc*16 + (lsel >> 1)*8;
            LDSM4(ah[0], ah[1], ah[2], ah[3],
                  sb + G_XG + (row*XGST + col)*2);
        }
        #pragma unroll
        for (int p = 0; p < 4; p++) {
            int brow = lrow + (lsel & 1)*8;
            int bcol = p*16 + (lsel >> 1)*8;
            u32 t0,t1,t2,t3;
            LDSM4T(t0,t1,t2,t3, wb + (brow*FWSTR + bcol)*2);
            MMA16816(acc[2*p],   ah, t0, t1);
            MMA16816(acc[2*p+1], ah, t2, t3);
        }
        __syncthreads();
    }

    int group = lane >> 2, tg = lane & 3;
    #pragma unroll
    for (int nt = 0; nt < 8; nt++)
        #pragma unroll
        for (int half = 0; half < 2; half++)
            #pragma unroll
            for (int j = 0; j < 2; j++) {
                int b = warp*16 + group + half*8;
                int o = nt*8 + tg*2 + j;
                float hc = tanh_f(acc[nt][half*2 + j] + bu[o]);
                float z  = g_Z[((size_t)n*Bb + b)*DOUT + o];
                float s  = st[((size_t)b*Nn + n)*DOUT + o];
                out[((size_t)b*Nn + n)*DOUT + o] = z*s + (1.f - z)*hc;
            }
}

// ---------------- launch ---------------------------------------------------
extern "C" void kernel_launch(void* const* d_in, const int* in_sizes, int n_in,
                              void* d_out, int out_size)
{
    const float* x    = (const float*)d_in[0];
    const float* st   = (const float*)d_in[1];
    const float* emb  = (const float*)d_in[2];
    const float* Wr_w = (const float*)d_in[3];
    const float* Wu_w = (const float*)d_in[4];
    const float* br_b = (const float*)d_in[5];
    const float* bu_b = (const float*)d_in[6];
    float* out = (float*)d_out;

    f16 *pAS, *pXh, *pYh;
    cudaGetSymbolAddress((void**)&pAS,  g_AS);
    cudaGetSymbolAddress((void**)&pXh,  g_Xh);
    cudaGetSymbolAddress((void**)&pYh,  g_Yh);
    f16* pA2 = pAS + (size_t)Nn*Nn;     // A^2 block (rows 2000..3999)

    cudaFuncSetAttribute(adj_pack,     cudaFuncAttributeMaxDynamicSharedMemorySize, ADJ_SMEM);
    cudaFuncSetAttribute(gate_kernel,  cudaFuncAttributeMaxDynamicSharedMemorySize, GATE_SMEM);
    cudaFuncSetAttribute(final_kernel, cudaFuncAttributeMaxDynamicSharedMemorySize, FIN_SMEM);
    cudaFuncSetAttribute(mma_gemm,     cudaFuncAttributeMaxDynamicSharedMemorySize, GSMEM_B);

    dim3 gA2((Nn + BN - 1)/BN, (Nn + BM - 1)/BM);        // (11, 16)
    dim3 gFused(CCOLS/BN, (2*Nn + BM - 1)/BM);           // (22, 32)
    dim3 gMix(99, (Nn + 63)/64, 2);                      // z=0: Wr, z=1: Wu

    // 7 launches; the fused conv GEMM sits at position 4 (the profiled slot).
    adj_pack<<<ADJB + PACKB, 256, ADJ_SMEM>>>(emb, x, st);              // 1
    mma_gemm<<<gA2, 256, GSMEM_B>>>(pAS, pAS, pA2, Nn, Nn, Nn);         // 2: A2 = A@A
    mix_mma<<<gMix, 256>>>(emb, Wr_w, Wu_w);                            // 3
    mma_gemm<<<gFused, 256, GSMEM_B>>>(pAS, pXh, pYh, 2*Nn, CCOLS, Nn); // 4: [Y1;Y2raw]
    gate_kernel<<<Nn, 128, GATE_SMEM>>>(emb, br_b, st);                 // 5
    mma_gemm<<<gFused, 256, GSMEM_B>>>(pAS, pXh, pYh, 2*Nn, CCOLS, Nn); // 6
    final_kernel<<<Nn, 128, FIN_SMEM>>>(emb, bu_b, st, out);            // 7
}